// round 8
// baseline (speedup 1.0000x reference)
#include <cuda_runtime.h>
#include <math.h>
#include <stdint.h>

#define NTOK 8192
#define DDIM 1024
#define HDIM 2048
#define MDIM 64
#define EEXP 8
#define HHALF 1024
#define ECAP 8192
#define NASSIGN (NTOK * 2)
#define S2C_SPLIT 16
#define EXP_SPLIT 8

// tf32-rounded: [X(perm) | s2c_W | We1 | We2 | c2s_W]
#define RN_X   0UL
#define RN_SW  8388608UL
#define RN_W1  8519680UL
#define RN_W2  9043968UL
#define RN_CW  9568256UL
#define RN_TOT 9699328UL
__device__ float g_rnd[RN_TOT];
__device__ float g_encWT[(size_t)HDIM * DDIM];   // enc_W^T [h][d], d k-permuted, tf32
__device__ float g_decWT[(size_t)DDIM * HDIM];   // dec_W^T [d][h], h k-permuted, tf32

__device__ float g_part_s2c[(size_t)S2C_SPLIT * NTOK * MDIM];
__device__ float g_cont[(size_t)NTOK * MDIM];
__device__ int   g_assign_e[NASSIGN];
__device__ float g_assign_w[NASSIGN];
__device__ int   g_count[EEXP];
__device__ int   g_bucket[EEXP * ECAP];
__device__ float g_part_exp[(size_t)EXP_SPLIT * NASSIGN * MDIM];
__device__ float g_outflat[(size_t)NTOK * MDIM];
__device__ float g_spk_moe[(size_t)NTOK * HDIM];  // h k-permuted
__device__ float g_decoded[(size_t)NTOK * DDIM];

__device__ __forceinline__ unsigned f2tf(float x) {
    unsigned u; asm("cvt.rna.tf32.f32 %0, %1;" : "=r"(u) : "f"(x)); return u;
}
__device__ __forceinline__ float rtf(float x) { return __uint_as_float(f2tf(x)); }
__device__ __forceinline__ float sigf(float x) { return 1.0f / (1.0f + expf(-x)); }
// k-permutation within 8-groups: k -> [0,4,1,5,2,6,3,7] positions
__device__ __forceinline__ int permk(int k) {
    int j = k & 7;
    return (k & ~7) | ((j < 4) ? (j << 1) : (((j - 4) << 1) | 1));
}
__device__ __forceinline__ void cp16(void* dst, const void* src) {
    unsigned d = (unsigned)__cvta_generic_to_shared(dst);
    asm volatile("cp.async.cg.shared.global [%0], [%1], 16;\n" :: "r"(d), "l"(src));
}
__device__ __forceinline__ void cp_commit() { asm volatile("cp.async.commit_group;\n"); }
template<int N> __device__ __forceinline__ void cp_wait() {
    asm volatile("cp.async.wait_group %0;\n" :: "n"(N));
}
__device__ __forceinline__ void mma_tf32(float c[4], const unsigned a[4], const unsigned b[2]) {
    asm volatile(
        "mma.sync.aligned.m16n8k8.row.col.f32.tf32.tf32.f32 "
        "{%0,%1,%2,%3}, {%4,%5,%6,%7}, {%8,%9}, {%0,%1,%2,%3};\n"
        : "+f"(c[0]), "+f"(c[1]), "+f"(c[2]), "+f"(c[3])
        : "r"(a[0]), "r"(a[1]), "r"(a[2]), "r"(a[3]), "r"(b[0]), "r"(b[1]));
}

// mma.sync geometry (expert fused + c2s, unchanged)
#define BM 128
#define BN 128
#define AS 20
#define BS1 136
#define STAGES 4
#define PIPE_FLOATS (STAGES * (BM * AS + 16 * BS1))
#define SPIKE_S 132
#define W2_S 72
#define W2_OFF PIPE_FLOATS
#define FUSED_SMEM ((PIPE_FLOATS + 128 * W2_S) * 4)
#define AS2 36
#define BS2 136
#define ST2 3
#define PIPE2_SMEM (ST2 * (BM * AS2 + 32 * BS2) * 4)

// fast_gemm geometry: [row][k] permuted, stride 24 words, BK=16
#define FST_RS 24
#define FST_STG (128 * FST_RS * 2)    // 6144 floats per stage (A then B)
#define ENC_ST 3
#define DEC_ST 4
#define ENC_W2OFF (ENC_ST * FST_STG)  // 18432
#define ENC_SMEM ((ENC_W2OFF + 128 * W2_S) * 4)   // 110592 B
#define DEC_SMEM (DEC_ST * FST_STG * 4)           // 98304 B

// ---------------------------------------------------------------------------
// Pre-round to tf32 (rna); X gets k-permuted columns; zero counts.
// ---------------------------------------------------------------------------
__global__ void round_all(const float* __restrict__ X,   const float* __restrict__ s2cW,
                          const float* __restrict__ We1, const float* __restrict__ We2,
                          const float* __restrict__ c2sW)
{
    if (blockIdx.x == 0 && threadIdx.x < EEXP) g_count[threadIdx.x] = 0;
    const size_t f = ((size_t)blockIdx.x * 256 + threadIdx.x) * 4;
    if (f >= RN_TOT) return;
    if (f < RN_SW) {
        // X: permute d (low 10 bits) within 8-groups. f is 4-aligned:
        // j = 0..3 map to base + rel + 2*j where rel = (f&4)?1:0.
        float4 v = *(const float4*)&X[f];
        const size_t base = f & ~7UL;
        const size_t rel  = (f & 4) ? 1 : 0;
        g_rnd[base + rel + 0] = rtf(v.x);
        g_rnd[base + rel + 2] = rtf(v.y);
        g_rnd[base + rel + 4] = rtf(v.z);
        g_rnd[base + rel + 6] = rtf(v.w);
        return;
    }
    const float* src; size_t off;
    if      (f < RN_W1) { src = s2cW; off = f - RN_SW; }
    else if (f < RN_W2) { src = We1;  off = f - RN_W1; }
    else if (f < RN_CW) { src = We2;  off = f - RN_W2; }
    else                { src = c2sW; off = f - RN_CW; }
    float4 v = *(const float4*)&src[off];
    v.x = rtf(v.x); v.y = rtf(v.y); v.z = rtf(v.z); v.w = rtf(v.w);
    *(float4*)&g_rnd[f] = v;
}

// Transpose + round + permute the written contiguous (k) index.
// out[c*R + permk(r)] = rtf(in[r*C + c]); grid (C/32, R/32), block (32,8)
__global__ void transpose_rtf(const float* __restrict__ in, float* __restrict__ out,
                              int R, int C)
{
    __shared__ float t[32][33];
    const int bx = blockIdx.x * 32, by = blockIdx.y * 32;
#pragma unroll
    for (int j = 0; j < 4; j++)
        t[threadIdx.y + j * 8][threadIdx.x] =
            in[(size_t)(by + threadIdx.y + j * 8) * C + bx + threadIdx.x];
    __syncthreads();
#pragma unroll
    for (int j = 0; j < 4; j++) {
        const int r = by + threadIdx.x;
        out[(size_t)(bx + threadIdx.y + j * 8) * R + permk(r)] =
            rtf(t[threadIdx.x][threadIdx.y + j * 8]);
    }
}

// ---------------------------------------------------------------------------
// fast_gemm: C[128,128] = A[bm0:+128, :K] @ BT[bn0:+128, :K]^T
// Both operands [row][k] in smem, k pre-permuted globally -> LDS.64 fragments.
//  FUSE=1 (enc): sigmoid -> tf32 spike smem -> mma.sync s2c chunk -> partials
//  FUSE=0 (dec): sigmoid -> Cout fp32 (row stride DDIM)
// ---------------------------------------------------------------------------
template<bool FUSE>
__global__ __launch_bounds__(256, 2)
void fast_gemm(const float* __restrict__ A, const float* __restrict__ BT,
               const float* __restrict__ bias, const float* __restrict__ W2,
               float* __restrict__ Cout, int K)
{
    constexpr int ST = FUSE ? ENC_ST : DEC_ST;
    extern __shared__ float sm[];
    float* spike = sm;                    // aliases pipeline (epilogue only)
    float* w2s   = sm + ENC_W2OFF;        // FUSE only

    const int tid = threadIdx.x, lane = tid & 31, w = tid >> 5;
    const int g = lane >> 2, tg = lane & 3;
    const int wm = w >> 2, wn = w & 3;
    const int bm0 = blockIdx.y * 128, bn0 = blockIdx.x * 128;

    if (FUSE) {
#pragma unroll
        for (int it = 0; it < 8; it++) {
            int idx = tid + it * 256;
            int r = idx >> 4, c4 = idx & 15;
            cp16(&w2s[r * W2_S + c4 * 4], &W2[(size_t)(bn0 + r) * MDIM + c4 * 4]);
        }
        cp_commit();
    }

    float c[4][4][4];
#pragma unroll
    for (int i = 0; i < 4; i++)
#pragma unroll
        for (int j = 0; j < 4; j++)
#pragma unroll
            for (int q = 0; q < 4; q++) c[i][j][q] = 0.0f;

    const int nk = K / 16;
    auto issue = [&](int st, int kt) {
        const int k0 = kt * 16;
        float* as = sm + st * FST_STG;
        float* bs = as + 128 * FST_RS;
#pragma unroll
        for (int it = 0; it < 2; it++) {
            int idx = tid + it * 256;
            int r = idx >> 2, c4 = idx & 3;
            cp16(&as[r * FST_RS + c4 * 4], &A[(size_t)(bm0 + r) * K + k0 + c4 * 4]);
        }
#pragma unroll
        for (int it = 0; it < 2; it++) {
            int idx = tid + it * 256;
            int r = idx >> 2, c4 = idx & 3;
            cp16(&bs[r * FST_RS + c4 * 4], &BT[(size_t)(bn0 + r) * K + k0 + c4 * 4]);
        }
    };

#pragma unroll
    for (int s = 0; s < ST - 1; s++) {
        if (s < nk) issue(s, s);
        cp_commit();
    }

    for (int kt = 0; kt < nk; kt++) {
        cp_wait<ST - 2>();
        __syncthreads();
        const int st = kt % ST;
        const float* as = sm + st * FST_STG;
        const float* bs = as + 128 * FST_RS;
#pragma unroll
        for (int ks = 0; ks < 2; ks++) {
            // A fragments: per mf two LDS.64 (rows g, g+8); B: one LDS.64 per nf
            unsigned a[4][4], b[4][2];
#pragma unroll
            for (int mf = 0; mf < 4; mf++) {
                const int m0 = wm * 64 + mf * 16;
                float2 lo = *(const float2*)&as[(m0 + g)     * FST_RS + ks * 8 + 2 * tg];
                float2 hi = *(const float2*)&as[(m0 + g + 8) * FST_RS + ks * 8 + 2 * tg];
                a[mf][0] = __float_as_uint(lo.x);
                a[mf][1] = __float_as_uint(hi.x);
                a[mf][2] = __float_as_uint(lo.y);
                a[mf][3] = __float_as_uint(hi.y);
            }
#pragma unroll
            for (int nf = 0; nf < 4; nf++) {
                const int n0 = wn * 32 + nf * 8 + g;
                float2 bb = *(const float2*)&bs[n0 * FST_RS + ks * 8 + 2 * tg];
                b[nf][0] = __float_as_uint(bb.x);
                b[nf][1] = __float_as_uint(bb.y);
            }
#pragma unroll
            for (int mf = 0; mf < 4; mf++)
#pragma unroll
                for (int nf = 0; nf < 4; nf++) mma_tf32(c[mf][nf], a[mf], b[nf]);
        }
        const int nxt = kt + ST - 1;
        if (nxt < nk) issue(nxt % ST, nxt);
        cp_commit();
    }

    cp_wait<0>();
    __syncthreads();

    if (FUSE) {
        // sigmoid -> tf32 spike tile (normal layout) in smem
#pragma unroll
        for (int mf = 0; mf < 4; mf++)
#pragma unroll
            for (int nf = 0; nf < 4; nf++) {
                const int col = wn * 32 + nf * 8 + 2 * tg;
                const int r0  = wm * 64 + mf * 16 + g;
#pragma unroll
                for (int h = 0; h < 2; h++) {
                    const int row = r0 + h * 8;
                    float v0 = rtf(sigf(c[mf][nf][h * 2 + 0] + bias[bn0 + col]));
                    float v1 = rtf(sigf(c[mf][nf][h * 2 + 1] + bias[bn0 + col + 1]));
                    *(float2*)&spike[row * SPIKE_S + col] = make_float2(v0, v1);
                }
            }
        __syncthreads();

        // mini GEMM: part[128x64] = spike(128x128) @ w2s(128x64)
        const int wm2 = w >> 1, wn2 = w & 1;
        float c2[2][4][4];
#pragma unroll
        for (int i = 0; i < 2; i++)
#pragma unroll
            for (int j = 0; j < 4; j++)
#pragma unroll
                for (int q = 0; q < 4; q++) c2[i][j][q] = 0.0f;
#pragma unroll
        for (int ks = 0; ks < 16; ks++) {
            unsigned a[2][4], b[4][2];
#pragma unroll
            for (int mf = 0; mf < 2; mf++) {
                const int m0 = wm2 * 32 + mf * 16;
                a[mf][0] = __float_as_uint(spike[(m0 + g)     * SPIKE_S + ks * 8 + tg]);
                a[mf][1] = __float_as_uint(spike[(m0 + g + 8) * SPIKE_S + ks * 8 + tg]);
                a[mf][2] = __float_as_uint(spike[(m0 + g)     * SPIKE_S + ks * 8 + tg + 4]);
                a[mf][3] = __float_as_uint(spike[(m0 + g + 8) * SPIKE_S + ks * 8 + tg + 4]);
            }
#pragma unroll
            for (int nf = 0; nf < 4; nf++) {
                const int n0 = wn2 * 32 + nf * 8 + g;
                b[nf][0] = __float_as_uint(w2s[(ks * 8 + tg)     * W2_S + n0]);
                b[nf][1] = __float_as_uint(w2s[(ks * 8 + tg + 4) * W2_S + n0]);
            }
#pragma unroll
            for (int mf = 0; mf < 2; mf++)
#pragma unroll
                for (int nf = 0; nf < 4; nf++) mma_tf32(c2[mf][nf], a[mf], b[nf]);
        }
        const size_t sb = (size_t)blockIdx.x * NTOK * MDIM;
#pragma unroll
        for (int mf = 0; mf < 2; mf++)
#pragma unroll
            for (int nf = 0; nf < 4; nf++) {
                const int col = wn2 * 32 + nf * 8 + 2 * tg;
                const int r0  = wm2 * 32 + mf * 16 + g;
#pragma unroll
                for (int h = 0; h < 2; h++) {
                    const int row = r0 + h * 8;
                    *(float2*)&Cout[sb + (size_t)(bm0 + row) * MDIM + col] =
                        make_float2(c2[mf][nf][h * 2 + 0], c2[mf][nf][h * 2 + 1]);
                }
            }
    } else {
        // decoder epilogue: sigmoid -> fp32 decoded (normal layout)
#pragma unroll
        for (int mf = 0; mf < 4; mf++)
#pragma unroll
            for (int nf = 0; nf < 4; nf++) {
                const int col = bn0 + wn * 32 + nf * 8 + 2 * tg;
                const int r0  = bm0 + wm * 64 + mf * 16 + g;
#pragma unroll
                for (int h = 0; h < 2; h++) {
                    const int row = r0 + h * 8;
                    float v0 = sigf(c[mf][nf][h * 2 + 0] + bias[col]);
                    float v1 = sigf(c[mf][nf][h * 2 + 1] + bias[col + 1]);
                    *(float2*)&Cout[(size_t)row * DDIM + col] = make_float2(v0, v1);
                }
            }
    }
}

// ---------------------------------------------------------------------------
// Expert fused mma.sync GEMM+GEMM (unchanged, passing since R4)
// ---------------------------------------------------------------------------
__global__ __launch_bounds__(256, 2)
void exp_gemm2(const float* __restrict__ A, const float* __restrict__ W1,
               const float* __restrict__ b1, const float* __restrict__ W2,
               float* __restrict__ Cpart,
               const int* __restrict__ bucket, const int* __restrict__ count)
{
    extern __shared__ float sm[];
    float* spike = sm;
    float* w2s   = sm + W2_OFF;

    const int tid = threadIdx.x, lane = tid & 31, w = tid >> 5;
    const int g = lane >> 2, tg = lane & 3;
    const int wm = w >> 2, wn = w & 3;
    const int bm0 = blockIdx.y * BM, bn0 = blockIdx.x * BN;
    const int e = blockIdx.z;

    const int cnt = count[e];
    if (bm0 >= cnt) return;

    const float* W1p = W1 + (size_t)e * MDIM * HHALF;
    const float* b1p = b1 + (size_t)e * HHALF;
    const float* W2p = W2 + (size_t)e * HHALF * MDIM;

    constexpr int ALD = (BM * 16) / (256 * 4);
    size_t aoff[ALD];
#pragma unroll
    for (int it = 0; it < ALD; it++) {
        int idx = tid + it * 256;
        int r = idx >> 2;
        int grow = bm0 + r;
        int rr = (grow < cnt) ? grow : (cnt - 1);
        aoff[it] = (size_t)(bucket[e * ECAP + rr] >> 1) * MDIM;
    }

#pragma unroll
    for (int it = 0; it < (128 * 64) / (256 * 4); it++) {
        int idx = tid + it * 256;
        int r = idx >> 4, c4 = idx & 15;
        cp16(&w2s[r * W2_S + c4 * 4], &W2p[(size_t)(bn0 + r) * MDIM + c4 * 4]);
    }
    cp_commit();

    float c[4][4][4];
#pragma unroll
    for (int i = 0; i < 4; i++)
#pragma unroll
        for (int j = 0; j < 4; j++)
#pragma unroll
            for (int q = 0; q < 4; q++) c[i][j][q] = 0.0f;

    const int nk = MDIM / 16;
    auto issue = [&](int st, int kt) {
        const int k0 = kt * 16;
        float* as = sm + st * (BM * AS);
        float* bs = sm + STAGES * (BM * AS) + st * (16 * BS1);
#pragma unroll
        for (int it = 0; it < ALD; it++) {
            int idx = tid + it * 256;
            int r = idx >> 2, c4 = idx & 3;
            cp16(&as[r * AS + c4 * 4], A + aoff[it] + k0 + c4 * 4);
        }
#pragma unroll
        for (int it = 0; it < (16 * BN) / (256 * 4); it++) {
            int idx = tid + it * 256;
            int r = idx >> 5, c4 = idx & 31;
            cp16(&bs[r * BS1 + c4 * 4], &W1p[(size_t)(k0 + r) * HHALF + bn0 + c4 * 4]);
        }
    };

#pragma unroll
    for (int s = 0; s < STAGES - 1; s++) {
        if (s < nk) issue(s, s);
        cp_commit();
    }
    for (int kt = 0; kt < nk; kt++) {
        cp_wait<STAGES - 2>();
        __syncthreads();
        const int st = kt % STAGES;
        const float* as = sm + st * (BM * AS);
        const float* bs = sm + STAGES * (BM * AS) + st * (16 * BS1);
#pragma unroll
        for (int ks = 0; ks < 2; ks++) {
            unsigned a[4][4], b[4][2];
#pragma unroll
            for (int mf = 0; mf < 4; mf++) {
                const int m0 = wm * 64 + mf * 16;
                a[mf][0] = __float_as_uint(as[(m0 + g)     * AS + ks * 8 + tg]);
                a[mf][1] = __float_as_uint(as[(m0 + g + 8) * AS + ks * 8 + tg]);
                a[mf][2] = __float_as_uint(as[(m0 + g)     * AS + ks * 8 + tg + 4]);
                a[mf][3] = __float_as_uint(as[(m0 + g + 8) * AS + ks * 8 + tg + 4]);
            }
#pragma unroll
            for (int nf = 0; nf < 4; nf++) {
                const int n0 = wn * 32 + nf * 8 + g;
                b[nf][0] = __float_as_uint(bs[(ks * 8 + tg)     * BS1 + n0]);
                b[nf][1] = __float_as_uint(bs[(ks * 8 + tg + 4) * BS1 + n0]);
            }
#pragma unroll
            for (int mf = 0; mf < 4; mf++)
#pragma unroll
                for (int nf = 0; nf < 4; nf++) mma_tf32(c[mf][nf], a[mf], b[nf]);
        }
        const int nxt = kt + STAGES - 1;
        if (nxt < nk) issue(nxt % STAGES, nxt);
        cp_commit();
    }

    cp_wait<0>();
    __syncthreads();
#pragma unroll
    for (int mf = 0; mf < 4; mf++)
#pragma unroll
        for (int nf = 0; nf < 4; nf++) {
            const int col = wn * 32 + nf * 8 + 2 * tg;
            const int r0  = wm * 64 + mf * 16 + g;
#pragma unroll
            for (int h = 0; h < 2; h++) {
                const int row = r0 + h * 8;
                float v0 = fmaxf(c[mf][nf][h * 2 + 0] + b1p[bn0 + col],     0.0f);
                float v1 = fmaxf(c[mf][nf][h * 2 + 1] + b1p[bn0 + col + 1], 0.0f);
                *(float2*)&spike[row * SPIKE_S + col] = make_float2(rtf(v0), rtf(v1));
            }
        }
    __syncthreads();

    const int wm2 = w >> 1, wn2 = w & 1;
    float c2[2][4][4];
#pragma unroll
    for (int i = 0; i < 2; i++)
#pragma unroll
        for (int j = 0; j < 4; j++)
#pragma unroll
            for (int q = 0; q < 4; q++) c2[i][j][q] = 0.0f;
#pragma unroll
    for (int ks = 0; ks < 16; ks++) {
        unsigned a[2][4], b[4][2];
#pragma unroll
        for (int mf = 0; mf < 2; mf++) {
            const int m0 = wm2 * 32 + mf * 16;
            a[mf][0] = __float_as_uint(spike[(m0 + g)     * SPIKE_S + ks * 8 + tg]);
            a[mf][1] = __float_as_uint(spike[(m0 + g + 8) * SPIKE_S + ks * 8 + tg]);
            a[mf][2] = __float_as_uint(spike[(m0 + g)     * SPIKE_S + ks * 8 + tg + 4]);
            a[mf][3] = __float_as_uint(spike[(m0 + g + 8) * SPIKE_S + ks * 8 + tg + 4]);
        }
#pragma unroll
        for (int nf = 0; nf < 4; nf++) {
            const int n0 = wn2 * 32 + nf * 8 + g;
            b[nf][0] = __float_as_uint(w2s[(ks * 8 + tg)     * W2_S + n0]);
            b[nf][1] = __float_as_uint(w2s[(ks * 8 + tg + 4) * W2_S + n0]);
        }
#pragma unroll
        for (int mf = 0; mf < 2; mf++)
#pragma unroll
            for (int nf = 0; nf < 4; nf++) mma_tf32(c2[mf][nf], a[mf], b[nf]);
    }
    const size_t sb = (size_t)blockIdx.x * NASSIGN * MDIM;
#pragma unroll
    for (int mf = 0; mf < 2; mf++)
#pragma unroll
        for (int nf = 0; nf < 4; nf++) {
            const int col = wn2 * 32 + nf * 8 + 2 * tg;
            const int r0  = wm2 * 32 + mf * 16 + g;
#pragma unroll
            for (int h = 0; h < 2; h++) {
                const int row = r0 + h * 8;
                if (bm0 + row < cnt) {
                    const int i = bucket[e * ECAP + bm0 + row];
                    *(float2*)&Cpart[sb + (size_t)i * MDIM + col] =
                        make_float2(c2[mf][nf][h * 2 + 0], c2[mf][nf][h * 2 + 1]);
                }
            }
        }
}

// ---------------------------------------------------------------------------
// c2s: plain mma.sync GEMM BK=32 3-stage; sigmoid; stores tf32-rounded and
// K-PERMUTED columns (spk_moe feeds the decoder's [row][k] layout).
// ---------------------------------------------------------------------------
__global__ __launch_bounds__(256, 2)
void c2s_gemm(const float* __restrict__ A, const float* __restrict__ W,
              const float* __restrict__ bias, float* __restrict__ C,
              int K, int Hout)
{
    extern __shared__ float sm[];
    const int tid = threadIdx.x, lane = tid & 31, w = tid >> 5;
    const int g = lane >> 2, tg = lane & 3;
    const int wm = w >> 2, wn = w & 3;
    const int bm0 = blockIdx.y * BM, bn0 = blockIdx.x * BN;

    float c[4][4][4];
#pragma unroll
    for (int i = 0; i < 4; i++)
#pragma unroll
        for (int j = 0; j < 4; j++)
#pragma unroll
            for (int q = 0; q < 4; q++) c[i][j][q] = 0.0f;

    const int nk = K / 32;
    auto issue = [&](int st, int kt) {
        const int k0 = kt * 32;
        float* as = sm + st * (BM * AS2);
        float* bs = sm + ST2 * (BM * AS2) + st * (32 * BS2);
#pragma unroll
        for (int it = 0; it < (BM * 32) / (256 * 4); it++) {
            int idx = tid + it * 256;
            int r = idx >> 3, c4 = idx & 7;
            cp16(&as[r * AS2 + c4 * 4], &A[(size_t)(bm0 + r) * K + k0 + c4 * 4]);
        }
#pragma unroll
        for (int it = 0; it < (32 * BN) / (256 * 4); it++) {
            int idx = tid + it * 256;
            int r = idx >> 5, c4 = idx & 31;
            cp16(&bs[r * BS2 + c4 * 4], &W[(size_t)(k0 + r) * Hout + bn0 + c4 * 4]);
        }
    };

#pragma unroll
    for (int s = 0; s < ST2 - 1; s++) {
        if (s < nk) issue(s, s);
        cp_commit();
    }
    for (int kt = 0; kt < nk; kt++) {
        cp_wait<ST2 - 2>();
        __syncthreads();
        const int st = kt % ST2;
        const float* as = sm + st * (BM * AS2);
        const float* bs = sm + ST2 * (BM * AS2) + st * (32 * BS2);
#pragma unroll
        for (int ks = 0; ks < 4; ks++) {
            unsigned a[4][4], b[4][2];
#pragma unroll
            for (int mf = 0; mf < 4; mf++) {
                const int m0 = wm * 64 + mf * 16;
                a[mf][0] = __float_as_uint(as[(m0 + g)     * AS2 + ks * 8 + tg]);
                a[mf][1] = __float_as_uint(as[(m0 + g + 8) * AS2 + ks * 8 + tg]);
                a[mf][2] = __float_as_uint(as[(m0 + g)     * AS2 + ks * 8 + tg + 4]);
                a[mf][3] = __float_as_uint(as[(m0 + g + 8) * AS2 + ks * 8 + tg + 4]);
            }
#pragma unroll
            for (int nf = 0; nf < 4; nf++) {
                const int n0 = wn * 32 + nf * 8 + g;
                b[nf][0] = __float_as_uint(bs[(ks * 8 + tg)     * BS2 + n0]);
                b[nf][1] = __float_as_uint(bs[(ks * 8 + tg + 4) * BS2 + n0]);
            }
#pragma unroll
            for (int mf = 0; mf < 4; mf++)
#pragma unroll
                for (int nf = 0; nf < 4; nf++) mma_tf32(c[mf][nf], a[mf], b[nf]);
        }
        const int nxt = kt + ST2 - 1;
        if (nxt < nk) issue(nxt % ST2, nxt);
        cp_commit();
    }

#pragma unroll
    for (int mf = 0; mf < 4; mf++)
#pragma unroll
        for (int nf = 0; nf < 4; nf++) {
            const int col = bn0 + wn * 32 + nf * 8 + 2 * tg;
            const int r0  = bm0 + wm * 64 + mf * 16 + g;
#pragma unroll
            for (int h = 0; h < 2; h++) {
                const int row = r0 + h * 8;
                float v0 = rtf(sigf(c[mf][nf][h * 2 + 0] + bias[col]));
                float v1 = rtf(sigf(c[mf][nf][h * 2 + 1] + bias[col + 1]));
                C[(size_t)row * Hout + permk(col)]     = v0;
                C[(size_t)row * Hout + permk(col + 1)] = v1;
            }
        }
}

// ---------------------------------------------------------------------------
__global__ void router_kernel(const float* __restrict__ part_s2c,
                              const float* __restrict__ s2c_b,
                              float* __restrict__ cont,
                              const float* __restrict__ rW1, const float* __restrict__ rb1,
                              const float* __restrict__ rW2, const float* __restrict__ rb2,
                              int* __restrict__ assign_e, float* __restrict__ assign_w)
{
    __shared__ float cs[64], hid[64], logit[8];
    const int n = blockIdx.x, t = threadIdx.x;

    float cv = s2c_b[t];
#pragma unroll
    for (int s = 0; s < S2C_SPLIT; s++)
        cv += part_s2c[(size_t)s * NTOK * MDIM + (size_t)n * MDIM + t];
    cont[(size_t)n * MDIM + t] = rtf(cv);
    cs[t] = cv;
    __syncthreads();

    float a = rb1[t];
#pragma unroll
    for (int m = 0; m < 64; m++) a = fmaf(cs[m], rW1[m * 64 + t], a);
    hid[t] = tanhf(a);
    __syncthreads();

    if (t < EEXP) {
        float l = rb2[t];
#pragma unroll
        for (int j = 0; j < 64; j++) l = fmaf(hid[j], rW2[j * EEXP + t], l);
        logit[t] = l;
    }
    __syncthreads();

    if (t == 0) {
        float mx = logit[0];
        for (int e = 1; e < EEXP; e++) mx = fmaxf(mx, logit[e]);
        float p[EEXP];
        for (int e = 0; e < EEXP; e++) p[e] = expf(logit[e] - mx);
        int i1 = 0;
        for (int e = 1; e < EEXP; e++) if (p[e] > p[i1]) i1 = e;
        int i2 = (i1 == 0) ? 1 : 0;
        for (int e = 0; e < EEXP; e++) if (e != i1 && p[e] > p[i2]) i2 = e;
        const float denom = p[i1] + p[i2];
        const int ids[2] = {i1, i2};
        const float ws[2] = {p[i1] / denom, p[i2] / denom};
#pragma unroll
        for (int k = 0; k < 2; k++) {
            const int i = n * 2 + k;
            assign_e[i] = ids[k];
            assign_w[i] = ws[k];
            const int slot = atomicAdd(&g_count[ids[k]], 1);
            g_bucket[ids[k] * ECAP + slot] = i;
        }
    }
}

__global__ void combine_kernel(const float* __restrict__ part_exp,
                               const int* __restrict__ ae, const float* __restrict__ aw,
                               const float* __restrict__ be2, float* __restrict__ outflat)
{
    const int i = blockIdx.x * 256 + threadIdx.x;
    const int n = i >> 6, m = i & 63;
    float acc = 0.0f;
#pragma unroll
    for (int k = 0; k < 2; k++) {
        const int idx = 2 * n + k;
        float s = be2[ae[idx] * MDIM + m];
#pragma unroll
        for (int sp = 0; sp < EXP_SPLIT; sp++)
            s += part_exp[(size_t)sp * NASSIGN * MDIM + (size_t)idx * MDIM + m];
        acc = fmaf(aw[idx], s, acc);
    }
    outflat[i] = rtf(acc);
}

__global__ void layernorm_kernel(const float* __restrict__ x,
                                 const float* __restrict__ g, const float* __restrict__ b,
                                 float* __restrict__ out)
{
    const int n = blockIdx.x, t = threadIdx.x;
    const float* row = x + (size_t)n * DDIM;
    float v[4];
    float s = 0.0f, s2 = 0.0f;
#pragma unroll
    for (int i = 0; i < 4; i++) {
        v[i] = row[t + i * 256];
        s += v[i]; s2 += v[i] * v[i];
    }
#pragma unroll
    for (int o = 16; o > 0; o >>= 1) {
        s  += __shfl_xor_sync(0xFFFFFFFFu, s, o);
        s2 += __shfl_xor_sync(0xFFFFFFFFu, s2, o);
    }
    __shared__ float sh1[8], sh2[8], mu_s, rstd_s;
    const int warp = t >> 5, lane = t & 31;
    if (lane == 0) { sh1[warp] = s; sh2[warp] = s2; }
    __syncthreads();
    if (t == 0) {
        float S = 0.0f, S2 = 0.0f;
        for (int wq = 0; wq < 8; wq++) { S += sh1[wq]; S2 += sh2[wq]; }
        float mu = S / (float)DDIM;
        mu_s = mu;
        rstd_s = rsqrtf(S2 / (float)DDIM - mu * mu + 1e-5f);
    }
    __syncthreads();
    const float mu = mu_s, rstd = rstd_s;
    float* orow = out + (size_t)n * DDIM;
#pragma unroll
    for (int i = 0; i < 4; i++) {
        int col = t + i * 256;
        orow[col] = (v[i] - mu) * rstd * g[col] + b[col];
    }
}

// ---------------------------------------------------------------------------
extern "C" void kernel_launch(void* const* d_in, const int* in_sizes, int n_in,
                              void* d_out, int out_size)
{
    const float* X     = (const float*)d_in[0];
    const float* enc_W = (const float*)d_in[1];
    const float* enc_b = (const float*)d_in[2];
    const float* s2c_W = (const float*)d_in[3];
    const float* s2c_b = (const float*)d_in[4];
    const float* rW1   = (const float*)d_in[5];
    const float* rb1   = (const float*)d_in[6];
    const float* rW2   = (const float*)d_in[7];
    const float* rb2   = (const float*)d_in[8];
    const float* We1   = (const float*)d_in[9];
    const float* be1   = (const float*)d_in[10];
    const float* We2   = (const float*)d_in[11];
    const float* be2   = (const float*)d_in[12];
    const float* c2s_W = (const float*)d_in[13];
    const float* c2s_b = (const float*)d_in[14];
    const float* dec_W = (const float*)d_in[15];
    const float* dec_b = (const float*)d_in[16];
    const float* ln_g  = (const float*)d_in[17];
    const float* ln_b  = (const float*)d_in[18];

    float *rnd, *encWT, *decWT, *part_s2c, *cont, *aw, *part_exp, *outflat, *spk_moe, *decoded;
    int *ae, *bucket, *count;
    cudaGetSymbolAddress((void**)&rnd,      g_rnd);
    cudaGetSymbolAddress((void**)&encWT,    g_encWT);
    cudaGetSymbolAddress((void**)&decWT,    g_decWT);
    cudaGetSymbolAddress((void**)&part_s2c, g_part_s2c);
    cudaGetSymbolAddress((void**)&cont,     g_cont);
    cudaGetSymbolAddress((void**)&ae,       g_assign_e);
    cudaGetSymbolAddress((void**)&aw,       g_assign_w);
    cudaGetSymbolAddress((void**)&count,    g_count);
    cudaGetSymbolAddress((void**)&bucket,   g_bucket);
    cudaGetSymbolAddress((void**)&part_exp, g_part_exp);
    cudaGetSymbolAddress((void**)&outflat,  g_outflat);
    cudaGetSymbolAddress((void**)&spk_moe,  g_spk_moe);
    cudaGetSymbolAddress((void**)&decoded,  g_decoded);

    const float* Xr    = rnd + RN_X;
    const float* s2cWr = rnd + RN_SW;
    const float* We1r  = rnd + RN_W1;
    const float* We2r  = rnd + RN_W2;
    const float* c2sWr = rnd + RN_CW;

    auto kEnc = fast_gemm<true>;
    auto kDec = fast_gemm<false>;
    cudaFuncSetAttribute(kEnc, cudaFuncAttributeMaxDynamicSharedMemorySize, ENC_SMEM);
    cudaFuncSetAttribute(kDec, cudaFuncAttributeMaxDynamicSharedMemorySize, DEC_SMEM);
    cudaFuncSetAttribute(exp_gemm2, cudaFuncAttributeMaxDynamicSharedMemorySize, FUSED_SMEM);
    cudaFuncSetAttribute(c2s_gemm,  cudaFuncAttributeMaxDynamicSharedMemorySize, PIPE2_SMEM);

    // 0) prep: round + permute X; transposed+permuted enc_W/dec_W; zero counts
    round_all<<<(RN_TOT / 4 + 255) / 256, 256>>>(X, s2c_W, We1, We2, c2s_W);
    transpose_rtf<<<dim3(HDIM / 32, DDIM / 32), dim3(32, 8)>>>(enc_W, encWT, DDIM, HDIM);
    transpose_rtf<<<dim3(DDIM / 32, HDIM / 32), dim3(32, 8)>>>(dec_W, decWT, HDIM, DDIM);

    // 1) fused encoder+s2c
    kEnc<<<dim3(S2C_SPLIT, NTOK / 128), 256, ENC_SMEM>>>(
        Xr, encWT, enc_b, s2cWr, part_s2c, DDIM);

    // 2) routing
    router_kernel<<<NTOK, 64>>>(part_s2c, s2c_b, cont, rW1, rb1, rW2, rb2, ae, aw);

    // 3) fused expert MLP
    exp_gemm2<<<dim3(EXP_SPLIT, ECAP / BM, EEXP), 256, FUSED_SMEM>>>(
        cont, We1r, be1, We2r, part_exp, bucket, count);

    // 4) combine
    combine_kernel<<<(NTOK * MDIM) / 256, 256>>>(part_exp, ae, aw, be2, outflat);

    // 5) c2s -> tf32-rounded, k-permuted spk_moe
    c2s_gemm<<<dim3(HDIM / BN, NTOK / BM), 256, PIPE2_SMEM>>>(
        outflat, c2sWr, c2s_b, spk_moe, MDIM, HDIM);

    // 6) decoder
    kDec<<<dim3(DDIM / 128, NTOK / 128), 256, DEC_SMEM>>>(
        spk_moe, decWT, dec_b, nullptr, decoded, HDIM);

    // 7) layernorm -> d_out
    layernorm_kernel<<<NTOK, 256>>>(decoded, ln_g, ln_b, (float*)d_out);
}